// round 12
// baseline (speedup 1.0000x reference)
#include <cuda_runtime.h>

// SpatialTransformer: out[b,c,y,x] = bilinear_sample_zeros(src[b,c], y+flow[b,0,y,x], x+flow[b,1,y,x])
// src [8,64,256,256] f32, flow [8,2,256,256] f32, out [8,64,256,256] f32.
//
// R11: R2 kernel (scattered LDG.32 gathers — proven optimal per-instruction for
// this access pattern) with the warp's spatial footprint remapped from 32x1 to
// 8x4. Smaller x-span per warp => fewer unique 32B sectors per gather
// instruction => fewer l1tex wavefronts on the binding pipe.
// Block = 256 threads covering a 32x8 pixel tile (warps = 4 across x 2 down).

#define B_ 8
#define C_ 64
#define H_ 256
#define W_ 256
#define PLANE (H_ * W_)
#define CPT 8   // channels per thread

__global__ __launch_bounds__(256) void st_2d_kernel(
    const float* __restrict__ src,
    const float* __restrict__ flow,
    float* __restrict__ out)
{
    const int t    = threadIdx.x;
    const int lane = t & 31;
    const int w    = t >> 5;           // warp 0..7

    // warp-internal 8x4 footprint; warps tile 4 across, 2 down -> block = 32x x 8y
    const int lx = lane & 7;
    const int ly = lane >> 3;
    const int x  = blockIdx.x * 32 + (w & 3) * 8 + lx;   // 0..255
    const int y  = blockIdx.y * 8  + (w >> 2) * 4 + ly;  // 0..255
    const int cg = blockIdx.z & 7;     // channel group 0..7
    const int b  = blockIdx.z >> 3;    // batch 0..7

    // ---- per-(b,y,x) prologue (identical math to R2) ----
    const int fbase = b * 2 * PLANE + y * W_ + x;
    const float py = (float)y + __ldg(flow + fbase);           // flow ch 0 = dy
    const float px = (float)x + __ldg(flow + fbase + PLANE);   // flow ch 1 = dx

    const float y0f = floorf(py);
    const float x0f = floorf(px);
    float wy1 = py - y0f;
    float wx1 = px - x0f;
    float wy0 = 1.0f - wy1;
    float wx0 = 1.0f - wx1;

    const int y0 = (int)y0f;
    const int x0 = (int)x0f;
    const int y1 = y0 + 1;
    const int x1 = x0 + 1;

    // zeros padding folded into 1D weights
    wy0 = ((unsigned)y0 < (unsigned)H_) ? wy0 : 0.0f;
    wy1 = ((unsigned)y1 < (unsigned)H_) ? wy1 : 0.0f;
    wx0 = ((unsigned)x0 < (unsigned)W_) ? wx0 : 0.0f;
    wx1 = ((unsigned)x1 < (unsigned)W_) ? wx1 : 0.0f;

    const float w00 = wy0 * wx0;
    const float w01 = wy0 * wx1;
    const float w10 = wy1 * wx0;
    const float w11 = wy1 * wx1;

    // clamped coords (invalid taps carry weight 0)
    const int yc0 = min(max(y0, 0), H_ - 1);
    const int yc1 = min(max(y1, 0), H_ - 1);
    const int xc0 = min(max(x0, 0), W_ - 1);
    const int xc1 = min(max(x1, 0), W_ - 1);

    const int o00 = yc0 * W_ + xc0;
    const int o01 = yc0 * W_ + xc1;
    const int o10 = yc1 * W_ + xc0;
    const int o11 = yc1 * W_ + xc1;

    // ---- channel loop (identical to R2) ----
    const int c0 = cg * CPT;
    const float* s = src + (size_t)(b * C_ + c0) * PLANE;
    float*       o = out + (size_t)(b * C_ + c0) * PLANE + y * W_ + x;

    #pragma unroll
    for (int c = 0; c < CPT; ++c) {
        const float v00 = __ldg(s + o00);
        const float v01 = __ldg(s + o01);
        const float v10 = __ldg(s + o10);
        const float v11 = __ldg(s + o11);
        o[c * PLANE] = w00 * v00 + w01 * v01 + w10 * v10 + w11 * v11;
        s += PLANE;
    }
}

extern "C" void kernel_launch(void* const* d_in, const int* in_sizes, int n_in,
                              void* d_out, int out_size)
{
    const float* src  = (const float*)d_in[0];
    const float* flow = (const float*)d_in[1];
    float* out = (float*)d_out;

    dim3 grid(W_ / 32, H_ / 8, B_ * (C_ / CPT));   // (8, 32, 64) = 16384 blocks
    dim3 block(256);
    st_2d_kernel<<<grid, block>>>(src, flow, out);
}

// round 13
// speedup vs baseline: 1.1880x; 1.1880x over previous
#include <cuda_runtime.h>

// SpatialTransformer: out[b,c,y,x] = bilinear_sample_zeros(src[b,c], y+flow[b,0,y,x], x+flow[b,1,y,x])
// src [8,64,256,256] f32, flow [8,2,256,256] f32, out [8,64,256,256] f32.
//
// R12: R2 mapping (warp = 32 consecutive x, scattered LDG.32 gathers — the
// empirically optimal structure across R8-R11) with CPT=16 to amortize the
// flow load + weight prologue, and an explicit 2-stage load pipeline so each
// warp keeps a steady 8 gathers in flight (hides L2 latency, smooths the
// l1tex queue that binds at 84.3%).

#define B_ 8
#define C_ 64
#define H_ 256
#define W_ 256
#define PLANE (H_ * W_)
#define CPT 16   // channels per thread

__global__ __launch_bounds__(256) void st_pipe_kernel(
    const float* __restrict__ src,
    const float* __restrict__ flow,
    float* __restrict__ out)
{
    const int x  = threadIdx.x;        // 0..255
    const int y  = blockIdx.x;         // 0..255
    const int cg = blockIdx.y;         // 0..3   (channel group of 16)
    const int b  = blockIdx.z;         // 0..7

    // ---- per-(b,y,x) prologue (identical math to R2) ----
    const int fbase = b * 2 * PLANE + y * W_ + x;
    const float py = (float)y + __ldg(flow + fbase);           // flow ch 0 = dy
    const float px = (float)x + __ldg(flow + fbase + PLANE);   // flow ch 1 = dx

    const float y0f = floorf(py);
    const float x0f = floorf(px);
    float wy1 = py - y0f;
    float wx1 = px - x0f;
    float wy0 = 1.0f - wy1;
    float wx0 = 1.0f - wx1;

    const int y0 = (int)y0f;
    const int x0 = (int)x0f;
    const int y1 = y0 + 1;
    const int x1 = x0 + 1;

    // zeros padding folded into 1D weights
    wy0 = ((unsigned)y0 < (unsigned)H_) ? wy0 : 0.0f;
    wy1 = ((unsigned)y1 < (unsigned)H_) ? wy1 : 0.0f;
    wx0 = ((unsigned)x0 < (unsigned)W_) ? wx0 : 0.0f;
    wx1 = ((unsigned)x1 < (unsigned)W_) ? wx1 : 0.0f;

    const float w00 = wy0 * wx0;
    const float w01 = wy0 * wx1;
    const float w10 = wy1 * wx0;
    const float w11 = wy1 * wx1;

    // clamped coords (invalid taps carry weight 0)
    const int yc0 = min(max(y0, 0), H_ - 1);
    const int yc1 = min(max(y1, 0), H_ - 1);
    const int xc0 = min(max(x0, 0), W_ - 1);
    const int xc1 = min(max(x1, 0), W_ - 1);

    const int o00 = yc0 * W_ + xc0;
    const int o01 = yc0 * W_ + xc1;
    const int o10 = yc1 * W_ + xc0;
    const int o11 = yc1 * W_ + xc1;

    // ---- channel loop with 2-stage load pipeline ----
    const int c0 = cg * CPT;
    const float* s = src + (size_t)(b * C_ + c0) * PLANE;
    float*       o = out + (size_t)(b * C_ + c0) * PLANE + y * W_ + x;

    // prologue: fetch channel 0's taps
    float a00 = __ldg(s + o00);
    float a01 = __ldg(s + o01);
    float a10 = __ldg(s + o10);
    float a11 = __ldg(s + o11);

    #pragma unroll
    for (int c = 0; c < CPT - 1; ++c) {
        const float* sn = s + PLANE;
        // prefetch next channel's taps (independent of current combine)
        const float n00 = __ldg(sn + o00);
        const float n01 = __ldg(sn + o01);
        const float n10 = __ldg(sn + o10);
        const float n11 = __ldg(sn + o11);

        o[c * PLANE] = w00 * a00 + w01 * a01 + w10 * a10 + w11 * a11;

        a00 = n00; a01 = n01; a10 = n10; a11 = n11;
        s = sn;
    }
    o[(CPT - 1) * PLANE] = w00 * a00 + w01 * a01 + w10 * a10 + w11 * a11;
}

extern "C" void kernel_launch(void* const* d_in, const int* in_sizes, int n_in,
                              void* d_out, int out_size)
{
    const float* src  = (const float*)d_in[0];
    const float* flow = (const float*)d_in[1];
    float* out = (float*)d_out;

    dim3 grid(H_, C_ / CPT, B_);   // (256, 4, 8) = 8192 blocks
    dim3 block(W_);                // 256 threads, one per x
    st_pipe_kernel<<<grid, block>>>(src, flow, out);
}